// round 2
// baseline (speedup 1.0000x reference)
#include <cuda_runtime.h>
#include <cuda_bf16.h>
#include <cstdint>

#define BB 32
#define DD 128
#define LC 2048
#define LQ 512
#define NEG (-1e30f)

// Scratch (device globals: allocation-free per harness rules)
__device__ float g_S[(size_t)BB*LC*LQ];     // 134 MB logits
__device__ float g_T[(size_t)BB*LQ*DD];     // S2^T @ Ct
__device__ float g_sub0[BB*LC];
__device__ float g_sub1[BB*LQ];
__device__ float g_rmax[BB*LC];
__device__ float g_rsum[BB*LC];
__device__ float g_cmax[BB*LQ];
__device__ float g_csum[BB*LQ];

// ---------------- sub0 / sub1 ----------------
__global__ void k_sub0(const float* __restrict__ C, const float* __restrict__ w) {
    int b = blockIdx.y;
    int c = blockIdx.x * 256 + threadIdx.x;
    const float* Cb = C + (size_t)b * DD * LC;
    float acc = 0.f;
#pragma unroll 8
    for (int d = 0; d < DD; d++) acc += Cb[(size_t)d * LC + c] * w[d];
    g_sub0[b * LC + c] = acc;
}

__global__ void k_sub1(const float* __restrict__ Q, const float* __restrict__ w) {
    int b = blockIdx.y;
    int q = blockIdx.x * 256 + threadIdx.x;
    const float* Qb = Q + (size_t)b * DD * LQ;
    float acc = 0.f;
#pragma unroll 8
    for (int d = 0; d < DD; d++) acc += Qb[(size_t)d * LQ + q] * w[d];
    g_sub1[b * LQ + q] = acc;
}

// ---------------- GEMM S: S[c][q] = sum_d C[d][c]*w[d]*Q[d][q] + sub0 + sub1 + bias
__global__ __launch_bounds__(256) void k_gemm_S(
    const float* __restrict__ C, const float* __restrict__ Q,
    const float* __restrict__ w4mlu, const float* __restrict__ bias) {
    __shared__ float As[16][64];  // [k=d][m=c]
    __shared__ float Bs[16][64];  // [k=d][n=q]
    int b = blockIdx.z;
    int m0 = blockIdx.y * 64;  // c
    int n0 = blockIdx.x * 64;  // q
    int tid = threadIdx.x;
    int tx = tid & 15, ty = tid >> 4;
    const float* Cb = C + (size_t)b * DD * LC + m0;
    const float* Qb = Q + (size_t)b * DD * LQ + n0;
    float acc[4][4] = {};
    for (int k0 = 0; k0 < DD; k0 += 16) {
        int r = tid >> 4, cc = (tid & 15) * 4;
        float4 v = *(const float4*)(Cb + (size_t)(k0 + r) * LC + cc);
        float w = w4mlu[k0 + r];
        As[r][cc] = v.x * w; As[r][cc + 1] = v.y * w;
        As[r][cc + 2] = v.z * w; As[r][cc + 3] = v.w * w;
        float4 u = *(const float4*)(Qb + (size_t)(k0 + r) * LQ + cc);
        Bs[r][cc] = u.x; Bs[r][cc + 1] = u.y; Bs[r][cc + 2] = u.z; Bs[r][cc + 3] = u.w;
        __syncthreads();
#pragma unroll
        for (int k = 0; k < 16; k++) {
            float4 a = *(float4*)&As[k][ty * 4];
            float4 bq = *(float4*)&Bs[k][tx * 4];
            acc[0][0] += a.x * bq.x; acc[0][1] += a.x * bq.y; acc[0][2] += a.x * bq.z; acc[0][3] += a.x * bq.w;
            acc[1][0] += a.y * bq.x; acc[1][1] += a.y * bq.y; acc[1][2] += a.y * bq.z; acc[1][3] += a.y * bq.w;
            acc[2][0] += a.z * bq.x; acc[2][1] += a.z * bq.y; acc[2][2] += a.z * bq.z; acc[2][3] += a.z * bq.w;
            acc[3][0] += a.w * bq.x; acc[3][1] += a.w * bq.y; acc[3][2] += a.w * bq.z; acc[3][3] += a.w * bq.w;
        }
        __syncthreads();
    }
    float bb = bias[0];
    float s1[4];
#pragma unroll
    for (int j = 0; j < 4; j++) s1[j] = g_sub1[b * LQ + n0 + tx * 4 + j];
#pragma unroll
    for (int i = 0; i < 4; i++) {
        int c = m0 + ty * 4 + i;
        float s0 = g_sub0[b * LC + c] + bb;
        float4 o;
        o.x = acc[i][0] + s0 + s1[0];
        o.y = acc[i][1] + s0 + s1[1];
        o.z = acc[i][2] + s0 + s1[2];
        o.w = acc[i][3] + s0 + s1[3];
        *(float4*)&g_S[((size_t)(b * LC + c)) * LQ + n0 + tx * 4] = o;
    }
}

// ---------------- row softmax stats (over q, masked by Qmask) ----------------
__global__ void k_rowstats(const float* __restrict__ Qmask) {
    int warp = threadIdx.x >> 5, lane = threadIdx.x & 31;
    int row = blockIdx.x * 8 + warp;   // in [0, B*LC)
    int b = row / LC;
    const float* Srow = g_S + (size_t)row * LQ;
    const float* Qm = Qmask + b * LQ;
    float vals[16];
    float m = -1e38f;
#pragma unroll
    for (int i = 0; i < 16; i++) {
        int q = lane + i * 32;
        float s = Srow[q];
        float msk = Qm[q];
        float l = s * msk + (1.f - msk) * NEG;
        vals[i] = l;
        m = fmaxf(m, l);
    }
#pragma unroll
    for (int o = 16; o; o >>= 1) m = fmaxf(m, __shfl_xor_sync(~0u, m, o));
    float sum = 0.f;
#pragma unroll
    for (int i = 0; i < 16; i++) sum += __expf(vals[i] - m);
#pragma unroll
    for (int o = 16; o; o >>= 1) sum += __shfl_xor_sync(~0u, sum, o);
    if (lane == 0) { g_rmax[row] = m; g_rsum[row] = sum; }
}

// ---------------- col softmax stats (over c, masked by Cmask) ----------------
__global__ void k_colstats(const float* __restrict__ Cmask) {
    __shared__ float sm[8][32], ss[8][32];
    int b = blockIdx.y;
    int q0 = blockIdx.x * 32;
    int qi = threadIdx.x & 31, cj = threadIdx.x >> 5;
    int q = q0 + qi;
    const float* Sb = g_S + (size_t)b * LC * LQ;
    const float* Cm = Cmask + b * LC;
    float m = -1e38f, s = 0.f;
    for (int c = cj; c < LC; c += 8) {
        float v = Sb[(size_t)c * LQ + q];
        float msk = Cm[c];
        float l = v * msk + (1.f - msk) * NEG;
        float nm = fmaxf(m, l);
        s = s * __expf(m - nm) + __expf(l - nm);
        m = nm;
    }
    sm[cj][qi] = m; ss[cj][qi] = s;
    __syncthreads();
    if (cj == 0) {
        float M = sm[0][qi], S = ss[0][qi];
#pragma unroll
        for (int j = 1; j < 8; j++) {
            float m2 = sm[j][qi], s2 = ss[j][qi];
            float nm = fmaxf(M, m2);
            S = S * __expf(M - nm) + s2 * __expf(m2 - nm);
            M = nm;
        }
        g_cmax[b * LQ + q] = M;
        g_csum[b * LQ + q] = S;
    }
}

// ---------------- GEMM T: T[q][d] = (1/csum[q]) * sum_c exp(masked(S)-cmax[q]) * C[d][c]
__global__ __launch_bounds__(256) void k_gemm_T(
    const float* __restrict__ C, const float* __restrict__ Cmask) {
    __shared__ float As[32][64];    // p2[k=c][m=q]
    __shared__ float Bs[32][132];   // Ct[k=c][n=d] (padded)
    __shared__ float s_cmax[64], s_csum[64];
    int b = blockIdx.y;
    int m0 = blockIdx.x * 64;  // q tile
    int tid = threadIdx.x;
    int tx = tid & 15, ty = tid >> 4;
    if (tid < 64) {
        s_cmax[tid] = g_cmax[b * LQ + m0 + tid];
        s_csum[tid] = g_csum[b * LQ + m0 + tid];
    }
    __syncthreads();
    const float* Sb = g_S + (size_t)b * LC * LQ;
    const float* Cb = C + (size_t)b * DD * LC;
    const float* Cm = Cmask + b * LC;
    float acc[4][8] = {};
    for (int k0 = 0; k0 < LC; k0 += 32) {
        {   // A tile: 32 c-rows x 64 q, with fused exp
            int r = tid >> 3, col = (tid & 7) * 8;
            float cm = Cm[k0 + r];
            float ng = (1.f - cm) * NEG;
            const float* src = Sb + (size_t)(k0 + r) * LQ + m0 + col;
            float4 v0 = *(const float4*)src;
            float4 v1 = *(const float4*)(src + 4);
            As[r][col + 0] = __expf(v0.x * cm + ng - s_cmax[col + 0]);
            As[r][col + 1] = __expf(v0.y * cm + ng - s_cmax[col + 1]);
            As[r][col + 2] = __expf(v0.z * cm + ng - s_cmax[col + 2]);
            As[r][col + 3] = __expf(v0.w * cm + ng - s_cmax[col + 3]);
            As[r][col + 4] = __expf(v1.x * cm + ng - s_cmax[col + 4]);
            As[r][col + 5] = __expf(v1.y * cm + ng - s_cmax[col + 5]);
            As[r][col + 6] = __expf(v1.z * cm + ng - s_cmax[col + 6]);
            As[r][col + 7] = __expf(v1.w * cm + ng - s_cmax[col + 7]);
        }
        {   // B tile: transpose-load C[d][c] -> Bs[c][d]
            int cc = (tid & 7) * 4;
            int d = tid >> 3;
#pragma unroll
            for (int dd = 0; dd < 4; dd++) {
                float4 v = *(const float4*)(Cb + (size_t)(d + dd * 32) * LC + k0 + cc);
                Bs[cc + 0][d + dd * 32] = v.x;
                Bs[cc + 1][d + dd * 32] = v.y;
                Bs[cc + 2][d + dd * 32] = v.z;
                Bs[cc + 3][d + dd * 32] = v.w;
            }
        }
        __syncthreads();
#pragma unroll 8
        for (int k = 0; k < 32; k++) {
            float4 a = *(float4*)&As[k][ty * 4];
            float4 b0 = *(float4*)&Bs[k][tx * 8];
            float4 b1 = *(float4*)&Bs[k][tx * 8 + 4];
            float av[4] = {a.x, a.y, a.z, a.w};
            float bv[8] = {b0.x, b0.y, b0.z, b0.w, b1.x, b1.y, b1.z, b1.w};
#pragma unroll
            for (int i = 0; i < 4; i++)
#pragma unroll
                for (int j = 0; j < 8; j++) acc[i][j] += av[i] * bv[j];
        }
        __syncthreads();
    }
#pragma unroll
    for (int i = 0; i < 4; i++) {
        int q = m0 + ty * 4 + i;
        float inv = 1.f / s_csum[ty * 4 + i];
        float* dst = &g_T[((size_t)(b * LQ + q)) * DD + tx * 8];
        float4 o0 = {acc[i][0] * inv, acc[i][1] * inv, acc[i][2] * inv, acc[i][3] * inv};
        float4 o1 = {acc[i][4] * inv, acc[i][5] * inv, acc[i][6] * inv, acc[i][7] * inv};
        *(float4*)dst = o0;
        *(float4*)(dst + 4) = o1;
    }
}

// ---------------- GEMM F: A = S1@Qt, Bm = S1@T, fused epilogue writes out ----
__global__ __launch_bounds__(256) void k_gemm_F(
    const float* __restrict__ C, const float* __restrict__ Q,
    const float* __restrict__ Qmask, float* __restrict__ out) {
    __shared__ float As[32][64];    // p1 (unnormalized) [k=q][m=c]
    __shared__ float BQ[32][128];   // Qt [k=q][n=d]
    __shared__ float BT[32][128];   // T  [k=q][n=d]
    __shared__ float s_rmax[64], s_rsum[64];
    int b = blockIdx.y;
    int m0 = blockIdx.x * 64;  // c tile
    int tid = threadIdx.x;
    int tx = tid & 15, ty = tid >> 4;
    if (tid < 64) {
        s_rmax[tid] = g_rmax[b * LC + m0 + tid];
        s_rsum[tid] = g_rsum[b * LC + m0 + tid];
    }
    __syncthreads();
    const float* Sb = g_S + (size_t)b * LC * LQ;
    const float* Qb = Q + (size_t)b * DD * LQ;
    const float* Tb = g_T + (size_t)b * LQ * DD;
    const float* Qm = Qmask + b * LQ;
    float accA[4][8] = {}, accB[4][8] = {};
    for (int k0 = 0; k0 < LQ; k0 += 32) {
        {   // A tile: 64 c-rows x 32 q, fused exp, stored transposed
            int m = tid >> 2, kc = (tid & 3) * 8;
            float rmx = s_rmax[m];
            const float* src = Sb + (size_t)(m0 + m) * LQ + k0 + kc;
            float4 v0 = *(const float4*)src;
            float4 v1 = *(const float4*)(src + 4);
            float vv[8] = {v0.x, v0.y, v0.z, v0.w, v1.x, v1.y, v1.z, v1.w};
#pragma unroll
            for (int ii = 0; ii < 8; ii++) {
                float msk = Qm[k0 + kc + ii];
                float l = vv[ii] * msk + (1.f - msk) * NEG;
                As[kc + ii][m] = __expf(l - rmx);
            }
        }
        {   // BQ: transpose-load Q[d][q] -> BQ[q][d]
            int cc = (tid & 7) * 4;
            int d = tid >> 3;
#pragma unroll
            for (int dd = 0; dd < 4; dd++) {
                float4 v = *(const float4*)(Qb + (size_t)(d + dd * 32) * LQ + k0 + cc);
                BQ[cc + 0][d + dd * 32] = v.x;
                BQ[cc + 1][d + dd * 32] = v.y;
                BQ[cc + 2][d + dd * 32] = v.z;
                BQ[cc + 3][d + dd * 32] = v.w;
            }
        }
        {   // BT: direct load T
            int r = tid >> 3, cc = (tid & 7) * 16;
            const float* src = Tb + (size_t)(k0 + r) * DD + cc;
#pragma unroll
            for (int u = 0; u < 4; u++) {
                float4 v = *(const float4*)(src + u * 4);
                *(float4*)&BT[r][cc + u * 4] = v;
            }
        }
        __syncthreads();
#pragma unroll 4
        for (int k = 0; k < 32; k++) {
            float4 a = *(float4*)&As[k][ty * 4];
            float4 q0 = *(float4*)&BQ[k][tx * 8];
            float4 q1 = *(float4*)&BQ[k][tx * 8 + 4];
            float4 t0 = *(float4*)&BT[k][tx * 8];
            float4 t1 = *(float4*)&BT[k][tx * 8 + 4];
            float av[4] = {a.x, a.y, a.z, a.w};
            float qv[8] = {q0.x, q0.y, q0.z, q0.w, q1.x, q1.y, q1.z, q1.w};
            float tv[8] = {t0.x, t0.y, t0.z, t0.w, t1.x, t1.y, t1.z, t1.w};
#pragma unroll
            for (int i = 0; i < 4; i++)
#pragma unroll
                for (int j = 0; j < 8; j++) {
                    accA[i][j] += av[i] * qv[j];
                    accB[i][j] += av[i] * tv[j];
                }
        }
        __syncthreads();
    }
    // epilogue: out[b][od][c], od in {d, 128+d, 256+d, 384+d}
    float inv[4];
#pragma unroll
    for (int i = 0; i < 4; i++) inv[i] = 1.f / s_rsum[ty * 4 + i];
    int cbase = m0 + ty * 4;
    size_t ob = ((size_t)b * 512) * 2048 + cbase;
#pragma unroll
    for (int j = 0; j < 8; j++) {
        int d = tx * 8 + j;
        float4 cv = *(const float4*)(C + ((size_t)b * DD + d) * LC + cbase);
        float4 av = {accA[0][j] * inv[0], accA[1][j] * inv[1],
                     accA[2][j] * inv[2], accA[3][j] * inv[3]};
        float4 bv = {accB[0][j] * inv[0], accB[1][j] * inv[1],
                     accB[2][j] * inv[2], accB[3][j] * inv[3]};
        float4 ca = {cv.x * av.x, cv.y * av.y, cv.z * av.z, cv.w * av.w};
        float4 cb = {cv.x * bv.x, cv.y * bv.y, cv.z * bv.z, cv.w * bv.w};
        *(float4*)&out[ob + (size_t)d * 2048] = cv;
        *(float4*)&out[ob + (size_t)(128 + d) * 2048] = av;
        *(float4*)&out[ob + (size_t)(256 + d) * 2048] = ca;
        *(float4*)&out[ob + (size_t)(384 + d) * 2048] = cb;
    }
}

extern "C" void kernel_launch(void* const* d_in, const int* in_sizes, int n_in,
                              void* d_out, int out_size) {
    (void)in_sizes; (void)n_in; (void)out_size;
    const float* C     = (const float*)d_in[0];
    const float* Q     = (const float*)d_in[1];
    const float* Cmask = (const float*)d_in[2];
    const float* Qmask = (const float*)d_in[3];
    const float* w4C   = (const float*)d_in[4];
    const float* w4Q   = (const float*)d_in[5];
    const float* w4mlu = (const float*)d_in[6];
    const float* bias  = (const float*)d_in[7];
    float* out = (float*)d_out;

    k_sub0<<<dim3(LC / 256, BB), 256>>>(C, w4C);
    k_sub1<<<dim3(LQ / 256, BB), 256>>>(Q, w4Q);
    k_gemm_S<<<dim3(LQ / 64, LC / 64, BB), 256>>>(C, Q, w4mlu, bias);
    k_rowstats<<<BB * LC / 8, 256>>>(Qmask);
    k_colstats<<<dim3(LQ / 32, BB), 256>>>(Cmask);
    k_gemm_T<<<dim3(LQ / 64, BB), 256>>>(C, Cmask);
    k_gemm_F<<<dim3(LC / 64, BB), 256>>>(C, Q, Qmask, out);
}

// round 4
// speedup vs baseline: 1.7902x; 1.7902x over previous
#include <cuda_runtime.h>
#include <cuda_bf16.h>
#include <cstdint>

#define BB 32
#define DD 128
#define LC 2048
#define LQ 512
#define NEG (-1e30f)

// smem layout (bytes)
#define O_AH 0
#define O_AL 10240
#define O_BH 20480
#define O_BL 25088
#define O_B2H 29696
#define O_B2L 34304
#define O_ST 38912
#define SMEM_SZ 39936

__device__ float g_S[(size_t)BB*LC*LQ];
__device__ float g_T[(size_t)BB*LQ*DD];          // fp32 [b][q][d]
__device__ float g_sub0[BB*LC], g_sub1[BB*LQ];
__device__ float g_rmax[BB*LC], g_rsum[BB*LC];
__device__ float g_cmax[BB*LQ], g_csum[BB*LQ];
__device__ __nv_bfloat16 g_Ch[(size_t)BB*DD*LC], g_Cl[(size_t)BB*DD*LC];     // [b][d][c]
__device__ __nv_bfloat16 g_Qh[(size_t)BB*DD*LQ], g_Ql[(size_t)BB*DD*LQ];     // [b][d][q]
__device__ __nv_bfloat16 g_CwTh[(size_t)BB*LC*DD], g_CwTl[(size_t)BB*LC*DD]; // [b][c][d] (*w4mlu)
__device__ __nv_bfloat16 g_QTh[(size_t)BB*LQ*DD], g_QTl[(size_t)BB*LQ*DD];   // [b][q][d]

__device__ __forceinline__ uint32_t smem_u32(const void* p) {
    uint32_t a;
    asm("{ .reg .u64 t; cvta.to.shared.u64 t, %1; cvt.u32.u64 %0, t; }" : "=r"(a) : "l"(p));
    return a;
}
__device__ __forceinline__ void split2(float x, __nv_bfloat16& h, __nv_bfloat16& l) {
    h = __float2bfloat16_rn(x);
    l = __float2bfloat16_rn(x - __bfloat162float(h));
}
__device__ __forceinline__ void ldsm4(uint32_t* r, uint32_t a) {
    asm volatile("ldmatrix.sync.aligned.m8n8.x4.shared.b16 {%0,%1,%2,%3}, [%4];"
        : "=r"(r[0]), "=r"(r[1]), "=r"(r[2]), "=r"(r[3]) : "r"(a));
}
__device__ __forceinline__ void ldsm4t(uint32_t* r, uint32_t a) {
    asm volatile("ldmatrix.sync.aligned.m8n8.x4.trans.shared.b16 {%0,%1,%2,%3}, [%4];"
        : "=r"(r[0]), "=r"(r[1]), "=r"(r[2]), "=r"(r[3]) : "r"(a));
}
__device__ __forceinline__ void mma_bf16(float* c, const uint32_t* a, const uint32_t* b) {
    asm volatile("mma.sync.aligned.m16n8k16.row.col.f32.bf16.bf16.f32 "
        "{%0,%1,%2,%3}, {%4,%5,%6,%7}, {%8,%9}, {%0,%1,%2,%3};"
        : "+f"(c[0]), "+f"(c[1]), "+f"(c[2]), "+f"(c[3])
        : "r"(a[0]), "r"(a[1]), "r"(a[2]), "r"(a[3]), "r"(b[0]), "r"(b[1]));
}
// One 32-wide K chunk of 3-term split MMA. acc[mf][nf][4]; warp tile 32x32.
__device__ __forceinline__ void mma_chunk(float acc[2][4][4], uint32_t uAl, uint32_t uBl) {
#pragma unroll
    for (int ks = 0; ks < 2; ks++) {
        uint32_t aH[2][4], aL[2][4], bH[8], bL[8];
#pragma unroll
        for (int mf = 0; mf < 2; mf++) {
            ldsm4(aH[mf], uAl + mf * 1280 + ks * 32);
            ldsm4(aL[mf], uAl + 10240 + mf * 1280 + ks * 32);
        }
#pragma unroll
        for (int nb = 0; nb < 2; nb++) {
            ldsm4t(&bH[nb * 4], uBl + ks * 2304 + nb * 32);
            ldsm4t(&bL[nb * 4], uBl + 4608 + ks * 2304 + nb * 32);
        }
#pragma unroll
        for (int mf = 0; mf < 2; mf++)
#pragma unroll
            for (int nf = 0; nf < 4; nf++) {
                mma_bf16(acc[mf][nf], aH[mf], &bH[nf * 2]);
                mma_bf16(acc[mf][nf], aH[mf], &bL[nf * 2]);
                mma_bf16(acc[mf][nf], aL[mf], &bH[nf * 2]);
            }
    }
}
// A tile 128x32 bf16 hi/lo -> smem (stride 40), gh/gl at tile origin
__device__ __forceinline__ void loadA(char* sm, const __nv_bfloat16* __restrict__ gh,
                                      const __nv_bfloat16* __restrict__ gl, int gs, int tid) {
#pragma unroll
    for (int i = 0; i < 2; i++) {
        int idx = tid * 2 + i, r = idx >> 2, c8 = (idx & 3) * 8;
        *(uint4*)(sm + r * 80 + c8 * 2) = *(const uint4*)(gh + (size_t)r * gs + c8);
        *(uint4*)(sm + 10240 + r * 80 + c8 * 2) = *(const uint4*)(gl + (size_t)r * gs + c8);
    }
}
// B tile 32x64 bf16 hi/lo -> smem (stride 72)
__device__ __forceinline__ void loadB(char* smB, const __nv_bfloat16* __restrict__ gh,
                                      const __nv_bfloat16* __restrict__ gl, int gs, int tid) {
    int r = tid >> 3, c8 = (tid & 7) * 8;
    *(uint4*)(smB + r * 144 + c8 * 2) = *(const uint4*)(gh + (size_t)r * gs + c8);
    *(uint4*)(smB + 4608 + r * 144 + c8 * 2) = *(const uint4*)(gl + (size_t)r * gs + c8);
}

// ---------------- prep ----------------
__global__ void k_split(const float4* __restrict__ src, int mode, int n4) {
    int i = blockIdx.x * 256 + threadIdx.x;
    if (i >= n4) return;
    __nv_bfloat162* hi = (__nv_bfloat162*)(mode ? g_Qh : g_Ch);
    __nv_bfloat162* lo = (__nv_bfloat162*)(mode ? g_Ql : g_Cl);
    float4 v = src[i];
    __nv_bfloat16 h0, h1, h2, h3, l0, l1, l2, l3;
    split2(v.x, h0, l0); split2(v.y, h1, l1); split2(v.z, h2, l2); split2(v.w, h3, l3);
    hi[2 * i] = {h0, h1}; hi[2 * i + 1] = {h2, h3};
    lo[2 * i] = {l0, l1}; lo[2 * i + 1] = {l2, l3};
}
__global__ void k_tsplit(const float* __restrict__ src, const float* __restrict__ scale,
                         int L, int mode) {
    __shared__ float t[32][33];
    __nv_bfloat16* hi = mode ? g_QTh : g_CwTh;
    __nv_bfloat16* lo = mode ? g_QTl : g_CwTl;
    int b = blockIdx.z, x0 = blockIdx.x * 32, d0 = blockIdx.y * 32;
    int tx = threadIdx.x, ty = threadIdx.y;
    const float* s = src + ((size_t)b * DD + d0) * L + x0;
#pragma unroll
    for (int i = 0; i < 4; i++) {
        int d = ty + i * 8;
        float v = s[(size_t)d * L + tx];
        if (scale) v *= scale[d0 + d];
        t[d][tx] = v;
    }
    __syncthreads();
#pragma unroll
    for (int i = 0; i < 4; i++) {
        int x = ty + i * 8;
        size_t o = ((size_t)b * L + x0 + x) * DD + d0 + tx;
        __nv_bfloat16 h, l;
        split2(t[tx][x], h, l);
        hi[o] = h; lo[o] = l;
    }
}
__global__ void k_sub(const float* __restrict__ X, const float* __restrict__ w, int L, int mode) {
    int b = blockIdx.y, x = blockIdx.x * 256 + threadIdx.x;
    const float* Xb = X + (size_t)b * DD * L;
    float acc = 0.f;
#pragma unroll 8
    for (int d = 0; d < DD; d++) acc += Xb[(size_t)d * L + x] * w[d];
    (mode ? g_sub1 : g_sub0)[b * L + x] = acc;
}

// ---------------- GEMM S: S[c][q] = CwT @ Q + sub0 + sub1 + bias ----------------
__global__ __launch_bounds__(256) void k_S(const float* __restrict__ bias) {
    extern __shared__ char sm[];
    int tid = threadIdx.x, lane = tid & 31, w = tid >> 5, wm = w & 3, wn = w >> 2;
    int b = blockIdx.z, m0 = blockIdx.y * 128, n0 = blockIdx.x * 64;
    const __nv_bfloat16* Ah = g_CwTh + ((size_t)b * LC + m0) * DD;
    const __nv_bfloat16* Al = g_CwTl + ((size_t)b * LC + m0) * DD;
    const __nv_bfloat16* Bh = g_Qh + (size_t)b * DD * LQ + n0;
    const __nv_bfloat16* Bl = g_Ql + (size_t)b * DD * LQ + n0;
    uint32_t su = smem_u32(sm);
    uint32_t uAl = su + (wm * 32 + (lane & 15)) * 80 + (lane >> 4) * 16;
    uint32_t uBl = su + O_BH + (lane & 15) * 144 + (wn * 32 + (lane >> 4) * 8) * 2;
    float acc[2][4][4] = {};
    for (int k0 = 0; k0 < DD; k0 += 32) {
        loadA(sm, Ah + k0, Al + k0, DD, tid);
        loadB(sm + O_BH, Bh + (size_t)k0 * LQ, Bl + (size_t)k0 * LQ, LQ, tid);
        __syncthreads();
        mma_chunk(acc, uAl, uBl);
        __syncthreads();
    }
    float bb = bias[0];
    int c0 = lane >> 2, nl = (lane & 3) * 2;
#pragma unroll
    for (int mf = 0; mf < 2; mf++)
#pragma unroll
        for (int rr = 0; rr < 2; rr++) {
            int gc = m0 + wm * 32 + mf * 16 + c0 + rr * 8;
            float s0 = g_sub0[b * LC + gc] + bb;
            float* row = g_S + ((size_t)(b * LC) + gc) * LQ + n0 + wn * 32;
            const float* s1 = g_sub1 + b * LQ + n0 + wn * 32;
#pragma unroll
            for (int nf = 0; nf < 4; nf++) {
                int q = nf * 8 + nl;
                row[q] = acc[mf][nf][rr * 2] + s0 + s1[q];
                row[q + 1] = acc[mf][nf][rr * 2 + 1] + s0 + s1[q + 1];
            }
        }
}

// ---------------- softmax stats ----------------
__global__ void k_rowstats(const float* __restrict__ Qmask) {
    int warp = threadIdx.x >> 5, lane = threadIdx.x & 31;
    int row = blockIdx.x * 8 + warp, b = row / LC;
    const float* Srow = g_S + (size_t)row * LQ;
    const float* Qm = Qmask + b * LQ;
    float vals[16], m = -1e38f;
#pragma unroll
    for (int i = 0; i < 16; i++) {
        int q = lane + i * 32;
        float msk = Qm[q];
        float l = Srow[q] * msk + (1.f - msk) * NEG;
        vals[i] = l; m = fmaxf(m, l);
    }
#pragma unroll
    for (int o = 16; o; o >>= 1) m = fmaxf(m, __shfl_xor_sync(~0u, m, o));
    float sum = 0.f;
#pragma unroll
    for (int i = 0; i < 16; i++) sum += __expf(vals[i] - m);
#pragma unroll
    for (int o = 16; o; o >>= 1) sum += __shfl_xor_sync(~0u, sum, o);
    if (lane == 0) { g_rmax[row] = m; g_rsum[row] = sum; }
}
__global__ void k_colstats(const float* __restrict__ Cmask) {
    __shared__ float sm[8][32], ss[8][32];
    int b = blockIdx.y, qi = threadIdx.x & 31, cj = threadIdx.x >> 5;
    int q = blockIdx.x * 32 + qi;
    const float* Sb = g_S + (size_t)b * LC * LQ;
    const float* Cm = Cmask + b * LC;
    float m = -1e38f, s = 0.f;
    for (int c = cj; c < LC; c += 8) {
        float msk = Cm[c];
        float l = Sb[(size_t)c * LQ + q] * msk + (1.f - msk) * NEG;
        float nm = fmaxf(m, l);
        s = s * __expf(m - nm) + __expf(l - nm); m = nm;
    }
    sm[cj][qi] = m; ss[cj][qi] = s;
    __syncthreads();
    if (cj == 0) {
        float M = sm[0][qi], S = ss[0][qi];
#pragma unroll
        for (int j = 1; j < 8; j++) {
            float nm = fmaxf(M, sm[j][qi]);
            S = S * __expf(M - nm) + ss[j][qi] * __expf(sm[j][qi] - nm); M = nm;
        }
        g_cmax[b * LQ + q] = M; g_csum[b * LQ + q] = S;
    }
}

// ---------------- GEMM T: T[q][d] = (1/csum[q]) * sum_c exp(S-cmax) * C[d][c] ----------------
__global__ __launch_bounds__(256) void k_T(const float* __restrict__ Cmask) {
    extern __shared__ char sm[];
    int tid = threadIdx.x, lane = tid & 31, w = tid >> 5, wm = w & 3, wn = w >> 2;
    int b = blockIdx.y, n0 = blockIdx.x * 64;
    float* st = (float*)(sm + O_ST);  // [0:64) cmax, [64:128) cinv
    if (tid < 64) {
        st[tid] = g_cmax[b * LQ + n0 + tid];
        st[64 + tid] = 1.f / g_csum[b * LQ + n0 + tid];
    }
    __syncthreads();
    const __nv_bfloat16* Ahp = g_Ch + (size_t)b * DD * LC;
    const __nv_bfloat16* Alp = g_Cl + (size_t)b * DD * LC;
    const float* Sb = g_S + (size_t)b * LC * LQ;
    const float* Cm = Cmask + b * LC;
    uint32_t su = smem_u32(sm);
    uint32_t uAl = su + (wm * 32 + (lane & 15)) * 80 + (lane >> 4) * 16;
    uint32_t uBl = su + O_BH + (lane & 15) * 144 + (wn * 32 + (lane >> 4) * 8) * 2;
    float acc[2][4][4] = {};
    for (int k0 = 0; k0 < LC; k0 += 32) {
        loadA(sm, Ahp + k0, Alp + k0, LC, tid);
        {   // B = exp(masked S[c][q] - cmax[q]), rows k=c
            int r = tid >> 3, c8 = (tid & 7) * 8;
            float cm = Cm[k0 + r], ng = (1.f - cm) * NEG;
            const float* src = Sb + (size_t)(k0 + r) * LQ + n0 + c8;
            __nv_bfloat16 h[8], l[8];
#pragma unroll
            for (int j = 0; j < 8; j++) {
                float e = __expf(src[j] * cm + ng - st[c8 + j]);
                split2(e, h[j], l[j]);
            }
            *(uint4*)(sm + O_BH + r * 144 + c8 * 2) = *(uint4*)h;
            *(uint4*)(sm + O_BL + r * 144 + c8 * 2) = *(uint4*)l;
        }
        __syncthreads();
        mma_chunk(acc, uAl, uBl);
        __syncthreads();
    }
    int c0 = lane >> 2, nl = (lane & 3) * 2;
#pragma unroll
    for (int mf = 0; mf < 2; mf++)
#pragma unroll
        for (int nf = 0; nf < 4; nf++)
#pragma unroll
            for (int rr = 0; rr < 2; rr++) {
                int d = wm * 32 + mf * 16 + c0 + rr * 8;
#pragma unroll
                for (int jj = 0; jj < 2; jj++) {
                    int ql = wn * 32 + nf * 8 + nl + jj;
                    g_T[((size_t)(b * LQ) + n0 + ql) * DD + d] =
                        acc[mf][nf][rr * 2 + jj] * st[64 + ql];
                }
            }
}

// ---------------- GEMM F: A = S1@Qt, Bm = S1@T; fused epilogue ----------------
__global__ __launch_bounds__(256) void k_F(const float* __restrict__ C,
                                           const float* __restrict__ Qmask,
                                           float* __restrict__ out) {
    extern __shared__ char sm[];
    int tid = threadIdx.x, lane = tid & 31, w = tid >> 5, wm = w & 3, wn = w >> 2;
    int b = blockIdx.z, m0 = blockIdx.x * 128, dbase = blockIdx.y * 64;
    float* st = (float*)(sm + O_ST);  // [0:128) rmax, [128:256) rinv
    if (tid < 128) {
        st[tid] = g_rmax[b * LC + m0 + tid];
        st[128 + tid] = 1.f / g_rsum[b * LC + m0 + tid];
    }
    __syncthreads();
    const float* Sb = g_S + ((size_t)(b * LC) + m0) * LQ;
    const float* Qm = Qmask + b * LQ;
    const __nv_bfloat16* BQh = g_QTh + (size_t)b * LQ * DD + dbase;
    const __nv_bfloat16* BQl = g_QTl + (size_t)b * LQ * DD + dbase;
    const float* Tb = g_T + (size_t)b * LQ * DD + dbase;
    uint32_t su = smem_u32(sm);
    uint32_t uAl = su + (wm * 32 + (lane & 15)) * 80 + (lane >> 4) * 16;
    uint32_t uBl = su + O_BH + (lane & 15) * 144 + (wn * 32 + (lane >> 4) * 8) * 2;
    uint32_t uB2l = uBl + (O_B2H - O_BH);
    float accA[2][4][4] = {}, accB[2][4][4] = {};
    for (int k0 = 0; k0 < LQ; k0 += 32) {
        {   // A = exp(masked S[c][q] - rmax[c]), 128x32
#pragma unroll
            for (int i = 0; i < 2; i++) {
                int idx = tid * 2 + i, r = idx >> 2, q8 = (idx & 3) * 8;
                float rmx = st[r];
                const float* src = Sb + (size_t)r * LQ + k0 + q8;
                __nv_bfloat16 h[8], l[8];
#pragma unroll
                for (int j = 0; j < 8; j++) {
                    float msk = Qm[k0 + q8 + j];
                    float e = __expf(src[j] * msk + (1.f - msk) * NEG - rmx);
                    split2(e, h[j], l[j]);
                }
                *(uint4*)(sm + r * 80 + q8 * 2) = *(uint4*)h;
                *(uint4*)(sm + O_AL + r * 80 + q8 * 2) = *(uint4*)l;
            }
        }
        loadB(sm + O_BH, BQh + (size_t)k0 * DD, BQl + (size_t)k0 * DD, DD, tid);
        {   // B2 = T fp32 -> hi/lo
            int r = tid >> 3, c8 = (tid & 7) * 8;
            const float* src = Tb + (size_t)(k0 + r) * DD + c8;
            __nv_bfloat16 h[8], l[8];
#pragma unroll
            for (int j = 0; j < 8; j++) split2(src[j], h[j], l[j]);
            *(uint4*)(sm + O_B2H + r * 144 + c8 * 2) = *(uint4*)h;
            *(uint4*)(sm + O_B2L + r * 144 + c8 * 2) = *(uint4*)l;
        }
        __syncthreads();
        mma_chunk(accA, uAl, uBl);
        mma_chunk(accB, uAl, uB2l);
        __syncthreads();
    }
    // epilogue via smem stage [d(64)][c(128)+4]
    float* stage = (float*)sm;
    int c0 = lane >> 2, nl = (lane & 3) * 2;
#pragma unroll
    for (int pass = 0; pass < 2; pass++) {
        float (*acc)[4][4] = pass ? accB : accA;
#pragma unroll
        for (int mf = 0; mf < 2; mf++)
#pragma unroll
            for (int nf = 0; nf < 4; nf++)
#pragma unroll
                for (int rr = 0; rr < 2; rr++) {
                    int ml = wm * 32 + mf * 16 + c0 + rr * 8;
                    float ri = st[128 + ml];
#pragma unroll
                    for (int jj = 0; jj < 2; jj++) {
                        int dl = wn * 32 + nf * 8 + nl + jj;
                        stage[dl * 132 + ml] = acc[mf][nf][rr * 2 + jj] * ri;
                    }
                }
        __syncthreads();
        for (int dd = 0; dd < 8; dd++) {
            int dl = w * 8 + dd, dg = dbase + dl;
            const float* Crow = C + ((size_t)b * DD + dg) * LC + m0;
            float* o = out + ((size_t)b * 512 + dg) * 2048 + m0;
#pragma unroll
            for (int s2 = 0; s2 < 4; s2++) {
                int cl = lane + s2 * 32;
                float cv = Crow[cl], v = stage[dl * 132 + cl];
                if (pass == 0) {
                    o[cl] = cv;
                    o[(size_t)128 * 2048 + cl] = v;
                    o[(size_t)256 * 2048 + cl] = cv * v;
                } else {
                    o[(size_t)384 * 2048 + cl] = cv * v;
                }
            }
        }
        __syncthreads();
    }
}

extern "C" void kernel_launch(void* const* d_in, const int* in_sizes, int n_in,
                              void* d_out, int out_size) {
    (void)in_sizes; (void)n_in; (void)out_size;
    const float* C     = (const float*)d_in[0];
    const float* Q     = (const float*)d_in[1];
    const float* Cmask = (const float*)d_in[2];
    const float* Qmask = (const float*)d_in[3];
    const float* w4C   = (const float*)d_in[4];
    const float* w4Q   = (const float*)d_in[5];
    const float* w4mlu = (const float*)d_in[6];
    const float* bias  = (const float*)d_in[7];
    float* out = (float*)d_out;

    k_split<<<(BB * DD * LC / 4 + 255) / 256, 256>>>((const float4*)C, 0, BB * DD * LC / 4);
    k_split<<<(BB * DD * LQ / 4 + 255) / 256, 256>>>((const float4*)Q, 1, BB * DD * LQ / 4);
    k_tsplit<<<dim3(LC / 32, DD / 32, BB), dim3(32, 8)>>>(C, w4mlu, LC, 0);
    k_tsplit<<<dim3(LQ / 32, DD / 32, BB), dim3(32, 8)>>>(Q, nullptr, LQ, 1);
    k_sub<<<dim3(LC / 256, BB), 256>>>(C, w4C, LC, 0);
    k_sub<<<dim3(LQ / 256, BB), 256>>>(Q, w4Q, LQ, 1);
    k_S<<<dim3(LQ / 64, LC / 128, BB), 256, SMEM_SZ>>>(bias);
    k_rowstats<<<BB * LC / 8, 256>>>(Qmask);
    k_colstats<<<dim3(LQ / 32, BB), 256>>>(Cmask);
    k_T<<<dim3(LQ / 64, BB), 256, SMEM_SZ>>>(Cmask);
    k_F<<<dim3(LC / 128, 2, BB), 256, SMEM_SZ>>>(C, Qmask, out);
}

// round 5
// speedup vs baseline: 1.9149x; 1.0696x over previous
#include <cuda_runtime.h>
#include <cuda_bf16.h>
#include <cstdint>

#define BB 32
#define DD 128
#define LC 2048
#define LQ 512
#define NEG (-1e30f)

__device__ float g_S[(size_t)BB*LC*LQ];
__device__ float g_T[(size_t)BB*LQ*DD];
__device__ float g_sub0[BB*LC], g_sub1[BB*LQ];
__device__ float g_rmax[BB*LC], g_rsum[BB*LC];
__device__ float g_cmax[BB*LQ], g_csum[BB*LQ];
__device__ float g_cpm[BB*16*LQ], g_cps[BB*16*LQ];
__device__ __nv_bfloat16 g_Ch[(size_t)BB*DD*LC], g_Cl[(size_t)BB*DD*LC];
__device__ __nv_bfloat16 g_Qh[(size_t)BB*DD*LQ], g_Ql[(size_t)BB*DD*LQ];
__device__ __nv_bfloat16 g_CwTh[(size_t)BB*LC*DD], g_CwTl[(size_t)BB*LC*DD];
__device__ __nv_bfloat16 g_QTh[(size_t)BB*LQ*DD], g_QTl[(size_t)BB*LQ*DD];

__device__ __forceinline__ uint32_t smem_u32(const void* p) {
    uint32_t a;
    asm("{ .reg .u64 t; cvta.to.shared.u64 t, %1; cvt.u32.u64 %0, t; }" : "=r"(a) : "l"(p));
    return a;
}
__device__ __forceinline__ void split2(float x, __nv_bfloat16& h, __nv_bfloat16& l) {
    h = __float2bfloat16_rn(x);
    l = __float2bfloat16_rn(x - __bfloat162float(h));
}
__device__ __forceinline__ void ldsm4(uint32_t* r, uint32_t a) {
    asm volatile("ldmatrix.sync.aligned.m8n8.x4.shared.b16 {%0,%1,%2,%3}, [%4];"
        : "=r"(r[0]), "=r"(r[1]), "=r"(r[2]), "=r"(r[3]) : "r"(a));
}
__device__ __forceinline__ void ldsm4t(uint32_t* r, uint32_t a) {
    asm volatile("ldmatrix.sync.aligned.m8n8.x4.trans.shared.b16 {%0,%1,%2,%3}, [%4];"
        : "=r"(r[0]), "=r"(r[1]), "=r"(r[2]), "=r"(r[3]) : "r"(a));
}
__device__ __forceinline__ void mma_bf16(float* c, const uint32_t* a, const uint32_t* b) {
    asm volatile("mma.sync.aligned.m16n8k16.row.col.f32.bf16.bf16.f32 "
        "{%0,%1,%2,%3}, {%4,%5,%6,%7}, {%8,%9}, {%0,%1,%2,%3};"
        : "+f"(c[0]), "+f"(c[1]), "+f"(c[2]), "+f"(c[3])
        : "r"(a[0]), "r"(a[1]), "r"(a[2]), "r"(a[3]), "r"(b[0]), "r"(b[1]));
}
// 3-term split MMA over K=32. A stride 80 (lo at +10240); B stride SB, lo at +LOFF.
template<int SB, int NF, int LOFF>
__device__ __forceinline__ void mma_chunk2(float acc[2][NF][4], uint32_t uA, uint32_t uB) {
#pragma unroll
    for (int ks = 0; ks < 2; ks++) {
        uint32_t aH[2][4], aL[2][4], bH[NF * 2], bL[NF * 2];
#pragma unroll
        for (int mf = 0; mf < 2; mf++) {
            ldsm4(aH[mf], uA + mf * 1280 + ks * 32);
            ldsm4(aL[mf], uA + 10240 + mf * 1280 + ks * 32);
        }
#pragma unroll
        for (int nb = 0; nb < NF / 2; nb++) {
            ldsm4t(&bH[nb * 4], uB + ks * 16 * SB + nb * 32);
            ldsm4t(&bL[nb * 4], uB + LOFF + ks * 16 * SB + nb * 32);
        }
#pragma unroll
        for (int mf = 0; mf < 2; mf++)
#pragma unroll
            for (int nf = 0; nf < NF; nf++) {
                mma_bf16(acc[mf][nf], aH[mf], &bH[nf * 2]);
                mma_bf16(acc[mf][nf], aH[mf], &bL[nf * 2]);
                mma_bf16(acc[mf][nf], aL[mf], &bH[nf * 2]);
            }
    }
}
// A tile 128x32 hi/lo (stride 80, lo +10240)
__device__ __forceinline__ void loadA32(char* sm, const __nv_bfloat16* __restrict__ gh,
                                        const __nv_bfloat16* __restrict__ gl, size_t gs, int tid) {
    int r = tid >> 1, c16 = (tid & 1) * 16;
    const char* sh = (const char*)(gh + (size_t)r * gs + c16);
    const char* sl = (const char*)(gl + (size_t)r * gs + c16);
    char* d = sm + r * 80 + c16 * 2;
    *(uint4*)d = *(const uint4*)sh;  *(uint4*)(d + 16) = *(const uint4*)(sh + 16);
    *(uint4*)(d + 10240) = *(const uint4*)sl;  *(uint4*)(d + 10256) = *(const uint4*)(sl + 16);
}
// B tile 32x128 hi/lo (stride 272, lo +8704)
__device__ __forceinline__ void loadB128(char* smB, const __nv_bfloat16* __restrict__ gh,
                                         const __nv_bfloat16* __restrict__ gl, size_t gs, int tid) {
    int r = tid >> 3, c16 = (tid & 7) * 16;
    const char* sh = (const char*)(gh + (size_t)r * gs + c16);
    const char* sl = (const char*)(gl + (size_t)r * gs + c16);
    char* d = smB + r * 272 + c16 * 2;
    *(uint4*)d = *(const uint4*)sh;  *(uint4*)(d + 16) = *(const uint4*)(sh + 16);
    *(uint4*)(d + 8704) = *(const uint4*)sl;  *(uint4*)(d + 8720) = *(const uint4*)(sl + 16);
}

// ---------------- prep ----------------
__global__ void k_split(const float4* __restrict__ src, int mode, int n4) {
    int i = blockIdx.x * 256 + threadIdx.x;
    if (i >= n4) return;
    __nv_bfloat162* hi = (__nv_bfloat162*)(mode ? g_Qh : g_Ch);
    __nv_bfloat162* lo = (__nv_bfloat162*)(mode ? g_Ql : g_Cl);
    float4 v = src[i];
    __nv_bfloat16 h0, h1, h2, h3, l0, l1, l2, l3;
    split2(v.x, h0, l0); split2(v.y, h1, l1); split2(v.z, h2, l2); split2(v.w, h3, l3);
    hi[2 * i] = {h0, h1}; hi[2 * i + 1] = {h2, h3};
    lo[2 * i] = {l0, l1}; lo[2 * i + 1] = {l2, l3};
}
__global__ void k_tsplit(const float* __restrict__ src, const float* __restrict__ scale,
                         int L, int mode) {
    __shared__ float t[32][33];
    __nv_bfloat16* hi = mode ? g_QTh : g_CwTh;
    __nv_bfloat16* lo = mode ? g_QTl : g_CwTl;
    int b = blockIdx.z, x0 = blockIdx.x * 32, d0 = blockIdx.y * 32;
    int tx = threadIdx.x, ty = threadIdx.y;
    const float* s = src + ((size_t)b * DD + d0) * L + x0;
#pragma unroll
    for (int i = 0; i < 4; i++) {
        int d = ty + i * 8;
        float v = s[(size_t)d * L + tx];
        if (scale) v *= scale[d0 + d];
        t[d][tx] = v;
    }
    __syncthreads();
#pragma unroll
    for (int i = 0; i < 4; i++) {
        int x = ty + i * 8;
        size_t o = ((size_t)b * L + x0 + x) * DD + d0 + tx;
        __nv_bfloat16 h, l;
        split2(t[tx][x], h, l);
        hi[o] = h; lo[o] = l;
    }
}
__global__ void k_sub(const float* __restrict__ X, const float* __restrict__ w, int L, int mode) {
    int b = blockIdx.y, x = blockIdx.x * 256 + threadIdx.x;
    const float* Xb = X + (size_t)b * DD * L;
    float acc = 0.f;
#pragma unroll 8
    for (int d = 0; d < DD; d++) acc += Xb[(size_t)d * L + x] * w[d];
    (mode ? g_sub1 : g_sub0)[b * L + x] = acc;
}

// ---------------- GEMM S: 128c x 128q, K=128 ----------------
#define SBUF 37888
__global__ __launch_bounds__(256) void k_S(const float* __restrict__ bias) {
    extern __shared__ char sm[];
    int tid = threadIdx.x, lane = tid & 31, w = tid >> 5, wm = w & 3, wn = w >> 2;
    int b = blockIdx.z, m0 = blockIdx.y * 128, n0 = blockIdx.x * 128;
    const __nv_bfloat16* Ah = g_CwTh + ((size_t)b * LC + m0) * DD;
    const __nv_bfloat16* Al = g_CwTl + ((size_t)b * LC + m0) * DD;
    const __nv_bfloat16* Bh = g_Qh + (size_t)b * DD * LQ + n0;
    const __nv_bfloat16* Bl = g_Ql + (size_t)b * DD * LQ + n0;
    uint32_t su = smem_u32(sm);
    uint32_t uA = su + (wm * 32 + (lane & 15)) * 80 + (lane >> 4) * 16;
    uint32_t uB = su + 20480 + (lane & 15) * 272 + (wn * 64 + (lane >> 4) * 8) * 2;
    float acc[2][8][4] = {};
    loadA32(sm, Ah, Al, DD, tid);
    loadB128(sm + 20480, Bh, Bl, LQ, tid);
    __syncthreads();
    for (int k = 0; k < 4; k++) {
        int off = (k & 1) * SBUF, noff = ((k + 1) & 1) * SBUF;
        if (k < 3) {
            loadA32(sm + noff, Ah + (k + 1) * 32, Al + (k + 1) * 32, DD, tid);
            loadB128(sm + noff + 20480, Bh + (size_t)(k + 1) * 32 * LQ,
                     Bl + (size_t)(k + 1) * 32 * LQ, LQ, tid);
        }
        mma_chunk2<272, 8, 8704>(acc, uA + off, uB + off);
        __syncthreads();
    }
    float bb = bias[0];
    int c0 = lane >> 2, nl = (lane & 3) * 2;
#pragma unroll
    for (int mf = 0; mf < 2; mf++)
#pragma unroll
        for (int rr = 0; rr < 2; rr++) {
            int gc = m0 + wm * 32 + mf * 16 + c0 + rr * 8;
            float s0 = g_sub0[b * LC + gc] + bb;
            float* row = g_S + ((size_t)(b * LC) + gc) * LQ + n0 + wn * 64;
            const float* s1 = g_sub1 + b * LQ + n0 + wn * 64;
#pragma unroll
            for (int nf = 0; nf < 8; nf++) {
                int q = nf * 8 + nl;
                row[q] = acc[mf][nf][rr * 2] + s0 + s1[q];
                row[q + 1] = acc[mf][nf][rr * 2 + 1] + s0 + s1[q + 1];
            }
        }
}

// ---------------- fused stats: rows + col partials, one S sweep ----------------
__global__ __launch_bounds__(256) void k_stats(const float* __restrict__ Cmask,
                                               const float* __restrict__ Qmask) {
    __shared__ float qm[LQ];
    __shared__ float cmk[128];
    int b = blockIdx.y, c0 = blockIdx.x * 128;
    int tid = threadIdx.x, w = tid >> 5, lane = tid & 31;
    for (int i = tid; i < LQ; i += 256) qm[i] = Qmask[b * LQ + i];
    if (tid < 128) cmk[tid] = Cmask[b * LC + c0 + tid];
    __syncthreads();
    const float* Sb = g_S + ((size_t)(b * LC) + c0) * LQ;
    // rows: warp per row, 16 rows/warp
    for (int i = 0; i < 16; i++) {
        int r = w * 16 + i;
        const float* row = Sb + (size_t)r * LQ;
        float vals[16], m = -1e38f;
#pragma unroll
        for (int j = 0; j < 16; j++) {
            float msk = qm[lane + j * 32];
            float l = row[lane + j * 32] * msk + (1.f - msk) * NEG;
            vals[j] = l; m = fmaxf(m, l);
        }
#pragma unroll
        for (int o = 16; o; o >>= 1) m = fmaxf(m, __shfl_xor_sync(~0u, m, o));
        float sum = 0.f;
#pragma unroll
        for (int j = 0; j < 16; j++) sum += __expf(vals[j] - m);
#pragma unroll
        for (int o = 16; o; o >>= 1) sum += __shfl_xor_sync(~0u, sum, o);
        if (lane == 0) { g_rmax[b * LC + c0 + r] = m; g_rsum[b * LC + c0 + r] = sum; }
    }
    // cols: 2 q per thread, max pass then sum pass (L2 hits)
#pragma unroll
    for (int h = 0; h < 2; h++) {
        int q = tid + h * 256;
        float m = -1e38f;
#pragma unroll 8
        for (int r = 0; r < 128; r++) {
            float cm = cmk[r];
            float l = Sb[(size_t)r * LQ + q] * cm + (1.f - cm) * NEG;
            m = fmaxf(m, l);
        }
        float s = 0.f;
#pragma unroll 8
        for (int r = 0; r < 128; r++) {
            float cm = cmk[r];
            float l = Sb[(size_t)r * LQ + q] * cm + (1.f - cm) * NEG;
            s += __expf(l - m);
        }
        int idx = (b * 16 + blockIdx.x) * LQ + q;
        g_cpm[idx] = m; g_cps[idx] = s;
    }
}
__global__ void k_cmerge() {
    int b = blockIdx.x, q = threadIdx.x;
    float M = -1e38f;
#pragma unroll
    for (int i = 0; i < 16; i++) M = fmaxf(M, g_cpm[(b * 16 + i) * LQ + q]);
    float S = 0.f;
#pragma unroll
    for (int i = 0; i < 16; i++)
        S += g_cps[(b * 16 + i) * LQ + q] * __expf(g_cpm[(b * 16 + i) * LQ + q] - M);
    g_cmax[b * LQ + q] = M; g_csum[b * LQ + q] = S;
}

// ---------------- GEMM T: T[q][d], M=d 128, N=q 64, K=c 2048 ----------------
#define TBUF 29696
#define T_ST 59392
__global__ __launch_bounds__(256) void k_T(const float* __restrict__ Cmask) {
    extern __shared__ char sm[];
    int tid = threadIdx.x, lane = tid & 31, w = tid >> 5, wm = w & 3, wn = w >> 2;
    int b = blockIdx.y, n0 = blockIdx.x * 64;
    float* st = (float*)(sm + T_ST);
    if (tid < 64) {
        st[tid] = g_cmax[b * LQ + n0 + tid];
        st[64 + tid] = 1.f / g_csum[b * LQ + n0 + tid];
    }
    __syncthreads();
    const __nv_bfloat16* Ahp = g_Ch + (size_t)b * DD * LC;
    const __nv_bfloat16* Alp = g_Cl + (size_t)b * DD * LC;
    const float* Sb = g_S + (size_t)b * LC * LQ;
    const float* Cm = Cmask + b * LC;
    uint32_t su = smem_u32(sm);
    uint32_t uA = su + (wm * 32 + (lane & 15)) * 80 + (lane >> 4) * 16;
    uint32_t uB = su + 20480 + (lane & 15) * 144 + (wn * 32 + (lane >> 4) * 8) * 2;
    int br = tid >> 3, bq = (tid & 7) * 8;
    float acc[2][4][4] = {};
#pragma unroll 1
    for (int k = -1; k < 64; k++) {
        if (k + 1 < 64) {  // build tiles k+1
            int noff = ((k + 1) & 1) * TBUF, kc = (k + 1) * 32;
            loadA32(sm + noff, Ahp + kc, Alp + kc, LC, tid);
            float cm = Cm[kc + br], ng = (1.f - cm) * NEG;
            const float* src = Sb + (size_t)(kc + br) * LQ + n0 + bq;
            __align__(16) __nv_bfloat16 hh[8], ll[8];
#pragma unroll
            for (int j = 0; j < 8; j++) {
                float e = __expf(src[j] * cm + ng - st[bq + j]);
                split2(e, hh[j], ll[j]);
            }
            char* d = sm + noff + 20480 + br * 144 + bq * 2;
            *(uint4*)d = *(uint4*)hh;
            *(uint4*)(d + 4608) = *(uint4*)ll;
        }
        if (k >= 0) mma_chunk2<144, 4, 4608>(acc, uA + (k & 1) * TBUF, uB + (k & 1) * TBUF);
        __syncthreads();
    }
    int c0 = lane >> 2, nl = (lane & 3) * 2;
#pragma unroll
    for (int mf = 0; mf < 2; mf++)
#pragma unroll
        for (int nf = 0; nf < 4; nf++)
#pragma unroll
            for (int rr = 0; rr < 2; rr++) {
                int d = wm * 32 + mf * 16 + c0 + rr * 8;
#pragma unroll
                for (int jj = 0; jj < 2; jj++) {
                    int ql = wn * 32 + nf * 8 + nl + jj;
                    g_T[((size_t)(b * LQ) + n0 + ql) * DD + d] =
                        acc[mf][nf][rr * 2 + jj] * st[64 + ql];
                }
            }
}

// ---------------- GEMM F: M=c 128, N=d 128, K=q 512; A & Bmat fused ----------------
#define FBUF 55296
#define F_ST 110592
#define F_QM 111616
__global__ __launch_bounds__(256) void k_F(const float* __restrict__ C,
                                           const float* __restrict__ Qmask,
                                           float* __restrict__ out) {
    extern __shared__ char sm[];
    int tid = threadIdx.x, lane = tid & 31, w = tid >> 5, wm = w & 3, wn = w >> 2;
    int b = blockIdx.x & 31, m0 = (blockIdx.x >> 5) * 128;
    float* st = (float*)(sm + F_ST);
    float* qm = (float*)(sm + F_QM);
    if (tid < 128) {
        st[tid] = g_rmax[b * LC + m0 + tid];
        st[128 + tid] = 1.f / g_rsum[b * LC + m0 + tid];
    }
    for (int i = tid; i < LQ; i += 256) qm[i] = Qmask[b * LQ + i];
    __syncthreads();
    const float* Sb = g_S + ((size_t)(b * LC) + m0) * LQ;
    const __nv_bfloat16* BQh = g_QTh + (size_t)b * LQ * DD;
    const __nv_bfloat16* BQl = g_QTl + (size_t)b * LQ * DD;
    const float* Tb = g_T + (size_t)b * LQ * DD;
    uint32_t su = smem_u32(sm);
    uint32_t uA = su + (wm * 32 + (lane & 15)) * 80 + (lane >> 4) * 16;
    uint32_t uBQ = su + 20480 + (lane & 15) * 272 + (wn * 64 + (lane >> 4) * 8) * 2;
    int ar = tid >> 1, aq = (tid & 1) * 16;
    int br = tid >> 3, bc = (tid & 7) * 16;
    float accA[2][8][4] = {}, accB[2][8][4] = {};
#pragma unroll 1
    for (int k = -1; k < 16; k++) {
        if (k + 1 < 16) {
            int noff = ((k + 1) & 1) * FBUF, kq = (k + 1) * 32;
            {   // A = exp(masked S - rmax)
                float rmx = st[ar];
                const float* src = Sb + (size_t)ar * LQ + kq + aq;
                __align__(16) __nv_bfloat16 hh[16], ll[16];
#pragma unroll
                for (int j = 0; j < 16; j++) {
                    float msk = qm[kq + aq + j];
                    float e = __expf(src[j] * msk + (1.f - msk) * NEG - rmx);
                    split2(e, hh[j], ll[j]);
                }
                char* d = sm + noff + ar * 80 + aq * 2;
                *(uint4*)d = *(uint4*)hh; *(uint4*)(d + 16) = *(uint4*)(hh + 8);
                *(uint4*)(d + 10240) = *(uint4*)ll; *(uint4*)(d + 10256) = *(uint4*)(ll + 8);
            }
            loadB128(sm + noff + 20480, BQh + (size_t)kq * DD, BQl + (size_t)kq * DD, DD, tid);
            {   // BT from fp32 T
                const float* src = Tb + (size_t)(kq + br) * DD + bc;
                __align__(16) __nv_bfloat16 hh[16], ll[16];
#pragma unroll
                for (int j = 0; j < 16; j++) split2(src[j], hh[j], ll[j]);
                char* d = sm + noff + 37888 + br * 272 + bc * 2;
                *(uint4*)d = *(uint4*)hh; *(uint4*)(d + 16) = *(uint4*)(hh + 8);
                *(uint4*)(d + 8704) = *(uint4*)ll; *(uint4*)(d + 8720) = *(uint4*)(ll + 8);
            }
        }
        if (k >= 0) {
            int off = (k & 1) * FBUF;
            mma_chunk2<272, 8, 8704>(accA, uA + off, uBQ + off);
            mma_chunk2<272, 8, 8704>(accB, uA + off, uBQ + 17408 + off);
        }
        __syncthreads();
    }
    // epilogue: stage [d][c] then coalesced writes
    float* stage = (float*)sm;
    int c0 = lane >> 2, nl = (lane & 3) * 2;
#pragma unroll 1
    for (int pass = 0; pass < 2; pass++) {
        float (*acc)[8][4] = pass ? accB : accA;
#pragma unroll
        for (int mf = 0; mf < 2; mf++)
#pragma unroll
            for (int nf = 0; nf < 8; nf++)
#pragma unroll
                for (int rr = 0; rr < 2; rr++) {
                    int ml = wm * 32 + mf * 16 + c0 + rr * 8;
                    float ri = st[128 + ml];
#pragma unroll
                    for (int jj = 0; jj < 2; jj++) {
                        int dl = wn * 64 + nf * 8 + nl + jj;
                        stage[dl * 132 + ml] = acc[mf][nf][rr * 2 + jj] * ri;
                    }
                }
        __syncthreads();
        for (int dd = 0; dd < 16; dd++) {
            int dl = w * 16 + dd;
            const float* Crow = C + ((size_t)b * DD + dl) * LC + m0;
            float* o = out + ((size_t)b * 512 + dl) * 2048 + m0;
#pragma unroll
            for (int s2 = 0; s2 < 4; s2++) {
                int cl = lane + s2 * 32;
                float cv = Crow[cl], v = stage[dl * 132 + cl];
                if (pass == 0) {
                    o[cl] = cv;
                    o[(size_t)128 * 2048 + cl] = v;
                    o[(size_t)256 * 2048 + cl] = cv * v;
                } else {
                    o[(size_t)384 * 2048 + cl] = cv * v;
                }
            }
        }
        __syncthreads();
    }
}

extern "C" void kernel_launch(void* const* d_in, const int* in_sizes, int n_in,
                              void* d_out, int out_size) {
    (void)in_sizes; (void)n_in; (void)out_size;
    const float* C     = (const float*)d_in[0];
    const float* Q     = (const float*)d_in[1];
    const float* Cmask = (const float*)d_in[2];
    const float* Qmask = (const float*)d_in[3];
    const float* w4C   = (const float*)d_in[4];
    const float* w4Q   = (const float*)d_in[5];
    const float* w4mlu = (const float*)d_in[6];
    const float* bias  = (const float*)d_in[7];
    float* out = (float*)d_out;

    const int SMEM_S = 2 * SBUF;          // 75776
    const int SMEM_T = T_ST + 512;        // 59904
    const int SMEM_F = F_QM + 2048;       // 113664
    cudaFuncSetAttribute(k_S, cudaFuncAttributeMaxDynamicSharedMemorySize, SMEM_S);
    cudaFuncSetAttribute(k_T, cudaFuncAttributeMaxDynamicSharedMemorySize, SMEM_T);
    cudaFuncSetAttribute(k_F, cudaFuncAttributeMaxDynamicSharedMemorySize, SMEM_F);

    k_split<<<(BB * DD * LC / 4 + 255) / 256, 256>>>((const float4*)C, 0, BB * DD * LC / 4);
    k_split<<<(BB * DD * LQ / 4 + 255) / 256, 256>>>((const float4*)Q, 1, BB * DD * LQ / 4);
    k_tsplit<<<dim3(LC / 32, DD / 32, BB), dim3(32, 8)>>>(C, w4mlu, LC, 0);
    k_tsplit<<<dim3(LQ / 32, DD / 32, BB), dim3(32, 8)>>>(Q, nullptr, LQ, 1);
    k_sub<<<dim3(LC / 256, BB), 256>>>(C, w4C, LC, 0);
    k_sub<<<dim3(LQ / 256, BB), 256>>>(Q, w4Q, LQ, 1);
    k_S<<<dim3(LQ / 128, LC / 128, BB), 256, SMEM_S>>>(bias);
    k_stats<<<dim3(LC / 128, BB), 256>>>(Cmask, Qmask);
    k_cmerge<<<BB, LQ>>>();
    k_T<<<dim3(LQ / 64, BB), 256, SMEM_T>>>(Cmask);
    k_F<<<dim3((LC / 128) * BB), 256, SMEM_F>>>(C, Qmask, out);
}